// round 1
// baseline (speedup 1.0000x reference)
#include <cuda_runtime.h>
#include <cstdint>

#define NN   100000
#define EE   20000
#define NNZV 1000000
#define DIM  128

// Scratch (allocs are forbidden; device globals are the sanctioned path)
__device__ float g_m[EE * DIM];   // 10.24 MB  hyperedge accumulator
__device__ float g_y[NN * DIM];   // 51.2  MB  node accumulator

__device__ __forceinline__ void red4(float* p, float4 v) {
    asm volatile("red.global.add.v4.f32 [%0], {%1,%2,%3,%4};"
                 :: "l"(p), "f"(v.x), "f"(v.y), "f"(v.z), "f"(v.w) : "memory");
}

__global__ void zero_kernel() {
    int tid = blockIdx.x * blockDim.x + threadIdx.x;
    int stride = gridDim.x * blockDim.x;
    float4* m4 = reinterpret_cast<float4*>(g_m);
    float4* y4 = reinterpret_cast<float4*>(g_y);
    const int M4 = EE * DIM / 4;
    const int Y4 = NN * DIM / 4;
    float4 z = make_float4(0.f, 0.f, 0.f, 0.f);
    for (int i = tid; i < M4; i += stride) m4[i] = z;
    for (int i = tid; i < Y4; i += stride) y4[i] = z;
}

// Phase 1: m[col] += dv[row]^-1/2 * X[row]   (warp per nnz entry, float4 per lane)
__global__ void scatter1_kernel(const float* __restrict__ X,
                                const int*   __restrict__ rows,
                                const int*   __restrict__ cols,
                                const float* __restrict__ dv) {
    int w = (blockIdx.x * blockDim.x + threadIdx.x) >> 5;
    if (w >= NNZV) return;
    int lane = threadIdx.x & 31;
    int r = __ldg(rows + w);
    int c = __ldg(cols + w);
    float s = rsqrtf(__ldg(dv + r));
    float4 v = __ldg(reinterpret_cast<const float4*>(X) + r * (DIM / 4) + lane);
    v.x *= s; v.y *= s; v.z *= s; v.w *= s;
    red4(g_m + c * DIM + lane * 4, v);
}

// Phase 2: y[row] += de[col]^-1 * m[col]
__global__ void scatter2_kernel(const int*   __restrict__ rows,
                                const int*   __restrict__ cols,
                                const float* __restrict__ de) {
    int w = (blockIdx.x * blockDim.x + threadIdx.x) >> 5;
    if (w >= NNZV) return;
    int lane = threadIdx.x & 31;
    int r = __ldg(rows + w);
    int c = __ldg(cols + w);
    float s = 1.0f / __ldg(de + c);
    float4 v = *(reinterpret_cast<const float4*>(g_m) + c * (DIM / 4) + lane);
    v.x *= s; v.y *= s; v.z *= s; v.w *= s;
    red4(g_y + r * DIM + lane * 4, v);
}

// out[n] = (dv[n]^-1/2 * y[n]) @ W     fp32 tiled GEMM, BM=128, BN=128(=full), K=128
// 256 threads, each computes an 8x8 micro-tile. Y staged k-major in smem.
__global__ __launch_bounds__(256, 1)
void gemm_kernel(const float* __restrict__ dv,
                 const float* __restrict__ W,
                 float* __restrict__ out) {
    extern __shared__ float smem[];
    float* Yt = smem;                 // [DIM][DIM] k-major: Yt[k*DIM + r]
    float* Ws = smem + DIM * DIM;     // [DIM][DIM] row-major: Ws[k*DIM + j]

    int tid = threadIdx.x;
    int block_row = blockIdx.x * 128;

    // Stage W (coalesced)
    for (int i = tid; i < DIM * (DIM / 4); i += 256) {
        int r = i >> 5, c4 = i & 31;
        float4 v = __ldg(reinterpret_cast<const float4*>(W) + r * (DIM / 4) + c4);
        *reinterpret_cast<float4*>(&Ws[r * DIM + c4 * 4]) = v;
    }
    // Stage Y transposed + dv^{-1/2} scale. Map: consecutive tids -> consecutive r
    // so STS is conflict-free (LDG is gather-ish but everything is L2-resident).
    for (int i = tid; i < (DIM / 4) * DIM; i += 256) {
        int r = i & 127, c4 = i >> 7;
        int n = block_row + r;
        float4 v = make_float4(0.f, 0.f, 0.f, 0.f);
        if (n < NN) {
            float s = rsqrtf(__ldg(dv + n));
            v = *(reinterpret_cast<const float4*>(g_y) + n * (DIM / 4) + c4);
            v.x *= s; v.y *= s; v.z *= s; v.w *= s;
        }
        Yt[(c4 * 4 + 0) * DIM + r] = v.x;
        Yt[(c4 * 4 + 1) * DIM + r] = v.y;
        Yt[(c4 * 4 + 2) * DIM + r] = v.z;
        Yt[(c4 * 4 + 3) * DIM + r] = v.w;
    }
    __syncthreads();

    int tx = tid & 15;   // output-col group (8 cols)
    int ty = tid >> 4;   // row group (8 rows)

    float acc[8][8];
#pragma unroll
    for (int i = 0; i < 8; i++)
#pragma unroll
        for (int j = 0; j < 8; j++) acc[i][j] = 0.f;

#pragma unroll 4
    for (int k = 0; k < DIM; k++) {
        float yf[8], wf[8];
        *reinterpret_cast<float4*>(&yf[0]) = *reinterpret_cast<float4*>(&Yt[k * DIM + ty * 8]);
        *reinterpret_cast<float4*>(&yf[4]) = *reinterpret_cast<float4*>(&Yt[k * DIM + ty * 8 + 4]);
        *reinterpret_cast<float4*>(&wf[0]) = *reinterpret_cast<float4*>(&Ws[k * DIM + tx * 8]);
        *reinterpret_cast<float4*>(&wf[4]) = *reinterpret_cast<float4*>(&Ws[k * DIM + tx * 8 + 4]);
#pragma unroll
        for (int i = 0; i < 8; i++)
#pragma unroll
            for (int j = 0; j < 8; j++)
                acc[i][j] += yf[i] * wf[j];
    }

#pragma unroll
    for (int i = 0; i < 8; i++) {
        int n = block_row + ty * 8 + i;
        if (n < NN) {
            float4 lo = make_float4(acc[i][0], acc[i][1], acc[i][2], acc[i][3]);
            float4 hi = make_float4(acc[i][4], acc[i][5], acc[i][6], acc[i][7]);
            *reinterpret_cast<float4*>(&out[n * DIM + tx * 8])     = lo;
            *reinterpret_cast<float4*>(&out[n * DIM + tx * 8 + 4]) = hi;
        }
    }
}

extern "C" void kernel_launch(void* const* d_in, const int* in_sizes, int n_in,
                              void* d_out, int out_size) {
    const float* X    = (const float*)d_in[0];
    const int*   rows = (const int*)  d_in[1];
    const int*   cols = (const int*)  d_in[2];
    const float* dv   = (const float*)d_in[3];
    const float* de   = (const float*)d_in[4];
    const float* W    = (const float*)d_in[5];
    float*       out  = (float*)d_out;

    zero_kernel<<<2048, 256>>>();

    // warp per nnz entry: NNZ warps = NNZ*32 threads
    long long total_threads = (long long)NNZV * 32;
    int blocks = (int)((total_threads + 255) / 256);
    scatter1_kernel<<<blocks, 256>>>(X, rows, cols, dv);
    scatter2_kernel<<<blocks, 256>>>(rows, cols, de);

    static const size_t GEMM_SMEM = 2 * DIM * DIM * sizeof(float);  // 128 KB
    cudaFuncSetAttribute(gemm_kernel, cudaFuncAttributeMaxDynamicSharedMemorySize,
                         (int)GEMM_SMEM);
    gemm_kernel<<<(NN + 127) / 128, 256, GEMM_SMEM>>>(dv, W, out);
}